// round 1
// baseline (speedup 1.0000x reference)
#include <cuda_runtime.h>
#include <math.h>

#define HN   24
#define DHD  128
#define TXT_ 512
#define IMG_ 1024
#define SALL 1536
#define HID_ 3072
#define IPD_ 1152
#define IPL_ 128

// ---------------- static scratch (allocation-free) ----------------
__device__ float g_q[IMG_ * HID_];
__device__ float g_k[IMG_ * HID_];
__device__ float g_v[IMG_ * HID_];
__device__ float g_eq[TXT_ * HID_];
__device__ float g_ek[TXT_ * HID_];
__device__ float g_ev[TXT_ * HID_];
__device__ float g_ipk[IPL_ * HID_];
__device__ float g_ipv[IPL_ * HID_];
__device__ float g_qf[HN * SALL * DHD];
__device__ float g_kf[HN * SALL * DHD];
__device__ float g_vf[HN * SALL * DHD];
__device__ float g_ipq[HN * IMG_ * DHD];
__device__ float g_ipkh[HN * IPL_ * DHD];
__device__ float g_ipvh[HN * IPL_ * DHD];
__device__ float g_S[HN * SALL * SALL];
__device__ float g_Sip[HN * IMG_ * IPL_];
__device__ float g_O[HN * SALL * DHD];
__device__ float g_ipO[HN * IMG_ * DHD];
__device__ float g_imgin[IMG_ * HID_];
__device__ float g_encin[TXT_ * HID_];

// ---------------- GEMM: C[M,N] = A[M,K] * op(B) + bias ----------------
// NT=1: B is [N,K] row-major (C = A B^T). NT=0: B is [K,N] row-major (C = A B).
// BM=BN=128, BK=16, 256 threads, 8x8 per thread (split 4+4).
// Requires M%128==0, N%128==0, K%16==0.
#define SPAD 132

template <int NT>
__global__ __launch_bounds__(256) void gemm_kernel(
    const float* __restrict__ A, const float* __restrict__ B,
    const float* __restrict__ bias, float* __restrict__ C,
    int M, int N, int K,
    long long sA, long long sB, long long sC)
{
    A += (long long)blockIdx.z * sA;
    B += (long long)blockIdx.z * sB;
    C += (long long)blockIdx.z * sC;

    __shared__ float As[16][SPAD];
    __shared__ float Bs[16][SPAD];

    int tid = threadIdx.x;
    int tr = tid >> 4;      // 0..15
    int tc = tid & 15;      // 0..15
    int m0 = blockIdx.y * 128;
    int n0 = blockIdx.x * 128;

    float acc[8][8];
#pragma unroll
    for (int i = 0; i < 8; i++)
#pragma unroll
        for (int j = 0; j < 8; j++) acc[i][j] = 0.f;

    for (int k0 = 0; k0 < K; k0 += 16) {
#pragma unroll
        for (int it = 0; it < 2; it++) {
            int p = tid + it * 256;         // 0..511
            {   // A tile: rows m0..m0+127, cols k0..k0+15 (transpose into As[k][m])
                int row = p >> 2;
                int kq = (p & 3) << 2;
                float4 a = *(const float4*)(A + (long long)(m0 + row) * K + k0 + kq);
                As[kq + 0][row] = a.x; As[kq + 1][row] = a.y;
                As[kq + 2][row] = a.z; As[kq + 3][row] = a.w;
            }
            if (NT) {   // B tile: rows n0..n0+127 of [N,K]
                int row = p >> 2;
                int kq = (p & 3) << 2;
                float4 b = *(const float4*)(B + (long long)(n0 + row) * K + k0 + kq);
                Bs[kq + 0][row] = b.x; Bs[kq + 1][row] = b.y;
                Bs[kq + 2][row] = b.z; Bs[kq + 3][row] = b.w;
            } else {    // B tile: rows k0..k0+15 of [K,N]
                int krow = p >> 5;
                int nq = (p & 31) << 2;
                float4 b = *(const float4*)(B + (long long)(k0 + krow) * N + n0 + nq);
                *(float4*)&Bs[krow][nq] = b;
            }
        }
        __syncthreads();

#pragma unroll
        for (int kk = 0; kk < 16; kk++) {
            float ra[8], rb[8];
            *(float4*)&ra[0] = *(float4*)&As[kk][tr * 4];
            *(float4*)&ra[4] = *(float4*)&As[kk][tr * 4 + 64];
            *(float4*)&rb[0] = *(float4*)&Bs[kk][tc * 4];
            *(float4*)&rb[4] = *(float4*)&Bs[kk][tc * 4 + 64];
#pragma unroll
            for (int i = 0; i < 8; i++)
#pragma unroll
                for (int j = 0; j < 8; j++)
                    acc[i][j] += ra[i] * rb[j];
        }
        __syncthreads();
    }

#pragma unroll
    for (int g = 0; g < 2; g++) {
#pragma unroll
        for (int i = 0; i < 4; i++) {
            int m = m0 + tr * 4 + g * 64 + i;
            int ai = g * 4 + i;
#pragma unroll
            for (int hb = 0; hb < 2; hb++) {
                int n = n0 + tc * 4 + hb * 64;
                float4 r;
                r.x = acc[ai][hb * 4 + 0];
                r.y = acc[ai][hb * 4 + 1];
                r.z = acc[ai][hb * 4 + 2];
                r.w = acc[ai][hb * 4 + 3];
                if (bias) {
                    r.x += bias[n + 0]; r.y += bias[n + 1];
                    r.z += bias[n + 2]; r.w += bias[n + 3];
                }
                *(float4*)(C + (long long)m * N + n) = r;
            }
        }
    }
}

// ---------------- heads + RMS (+ optional RoPE on concat) ----------------
// grid (SALL, HN), block 128. s<TXT: encoder source+weight; else image.
__global__ void build_qk_rope(const float* __restrict__ enc_lin,
                              const float* __restrict__ img_lin,
                              const float* __restrict__ w_enc,
                              const float* __restrict__ w_img,
                              const float* __restrict__ cosb,
                              const float* __restrict__ sinb,
                              float* __restrict__ dst)
{
    int s = blockIdx.x;
    int h = blockIdx.y;
    int d = threadIdx.x;
    const float* src;
    const float* w;
    if (s < TXT_) { src = enc_lin + (long long)s * HID_; w = w_enc; }
    else          { src = img_lin + (long long)(s - TXT_) * HID_; w = w_img; }
    float x = src[h * DHD + d];
    float ss = x * x;
#pragma unroll
    for (int o = 16; o; o >>= 1) ss += __shfl_xor_sync(0xffffffffu, ss, o);
    __shared__ float sred[4];
    int lane = d & 31, wid = d >> 5;
    if (lane == 0) sred[wid] = ss;
    __syncthreads();
    ss = sred[0] + sred[1] + sred[2] + sred[3];
    float r = rsqrtf(ss * (1.0f / DHD) + 1e-6f);
    float xn = x * r * w[d];
    float partner = __shfl_xor_sync(0xffffffffu, xn, 1);
    float rot = (d & 1) ? partner : -partner;
    long long si = (long long)s * DHD + d;
    dst[((long long)h * SALL + s) * DHD + d] = xn * cosb[si] + rot * sinb[si];
}

// grid (Srows, HN), block 128. dst[h][s][d] = rms(src[s, h*128+d]) * w[d]
__global__ void build_rms(const float* __restrict__ src, const float* __restrict__ w,
                          float* __restrict__ dst, int Srows)
{
    int s = blockIdx.x;
    int h = blockIdx.y;
    int d = threadIdx.x;
    float x = src[(long long)s * HID_ + h * DHD + d];
    float ss = x * x;
#pragma unroll
    for (int o = 16; o; o >>= 1) ss += __shfl_xor_sync(0xffffffffu, ss, o);
    __shared__ float sred[4];
    int lane = d & 31, wid = d >> 5;
    if (lane == 0) sred[wid] = ss;
    __syncthreads();
    ss = sred[0] + sred[1] + sred[2] + sred[3];
    float r = rsqrtf(ss * (1.0f / DHD) + 1e-6f);
    dst[((long long)h * Srows + s) * DHD + d] = x * r * w[d];
}

// grid (SALL, HN), block 128: vf concat reshape
__global__ void build_v_concat(const float* __restrict__ enc, const float* __restrict__ img,
                               float* __restrict__ dst)
{
    int s = blockIdx.x, h = blockIdx.y, d = threadIdx.x;
    float x = (s < TXT_) ? enc[(long long)s * HID_ + h * DHD + d]
                         : img[(long long)(s - TXT_) * HID_ + h * DHD + d];
    dst[((long long)h * SALL + s) * DHD + d] = x;
}

// grid (Srows, HN), block 128: plain reshape to heads
__global__ void build_heads(const float* __restrict__ src, float* __restrict__ dst, int Srows)
{
    int s = blockIdx.x, h = blockIdx.y, d = threadIdx.x;
    dst[((long long)h * Srows + s) * DHD + d] = src[(long long)s * HID_ + h * DHD + d];
}

// ---------------- softmax over rows (scale applied pre-exp) ----------------
// grid = total rows, block 256, ncols <= 1536
__global__ void softmax_rows(float* __restrict__ S, int ncols, float scale)
{
    long long row = blockIdx.x;
    float* p = S + row * (long long)ncols;
    int tid = threadIdx.x;
    float lv[6];
    int cnt = 0;
    float mx = -INFINITY;
    for (int j = tid; j < ncols; j += 256) {
        float v = p[j] * scale;
        lv[cnt++] = v;
        mx = fmaxf(mx, v);
    }
    __shared__ float sred[8];
    int lane = tid & 31, wid = tid >> 5;
#pragma unroll
    for (int o = 16; o; o >>= 1) mx = fmaxf(mx, __shfl_xor_sync(0xffffffffu, mx, o));
    if (lane == 0) sred[wid] = mx;
    __syncthreads();
    mx = sred[0];
#pragma unroll
    for (int i = 1; i < 8; i++) mx = fmaxf(mx, sred[i]);
    __syncthreads();
    float sum = 0.f;
    for (int c = 0; c < cnt; c++) {
        float e = expf(lv[c] - mx);
        lv[c] = e;
        sum += e;
    }
#pragma unroll
    for (int o = 16; o; o >>= 1) sum += __shfl_xor_sync(0xffffffffu, sum, o);
    if (lane == 0) sred[wid] = sum;
    __syncthreads();
    sum = sred[0];
#pragma unroll
    for (int i = 1; i < 8; i++) sum += sred[i];
    float inv = 1.0f / sum;
    cnt = 0;
    for (int j = tid; j < ncols; j += 256) p[j] = lv[cnt++] * inv;
}

// ---------------- merge + bbox mask ----------------
// grid (IMG_, HN), block 128
__global__ void merge_img(const float* __restrict__ O, const float* __restrict__ ipO,
                          float* __restrict__ dst)
{
    int l = blockIdx.x, h = blockIdx.y, d = threadIdx.x;
    int row = l >> 5, col = l & 31;
    float m = (row >= 8 && row < 24 && col >= 8 && col < 24) ? 1.0f : 0.0f;
    dst[(long long)l * HID_ + h * DHD + d] =
        O[((long long)h * SALL + TXT_ + l) * DHD + d] +
        m * ipO[((long long)h * IMG_ + l) * DHD + d];
}

// grid (TXT_, HN), block 128
__global__ void merge_enc(const float* __restrict__ O, float* __restrict__ dst)
{
    int s = blockIdx.x, h = blockIdx.y, d = threadIdx.x;
    dst[(long long)s * HID_ + h * DHD + d] = O[((long long)h * SALL + s) * DHD + d];
}

// ---------------- launch ----------------
extern "C" void kernel_launch(void* const* d_in, const int* in_sizes, int n_in,
                              void* d_out, int out_size)
{
    const float* hidden   = (const float*)d_in[0];
    const float* enc_hs   = (const float*)d_in[1];
    const float* ip_hs    = (const float*)d_in[2];
    const float* rope_cos = (const float*)d_in[3];
    const float* rope_sin = (const float*)d_in[4];
    const float* Wq  = (const float*)d_in[5];
    const float* bq  = (const float*)d_in[6];
    const float* Wk  = (const float*)d_in[7];
    const float* bk  = (const float*)d_in[8];
    const float* Wv  = (const float*)d_in[9];
    const float* bv  = (const float*)d_in[10];
    const float* norm_q_w = (const float*)d_in[11];
    const float* norm_k_w = (const float*)d_in[12];
    const float* Wq_add = (const float*)d_in[13];
    const float* bq_add = (const float*)d_in[14];
    const float* Wk_add = (const float*)d_in[15];
    const float* bk_add = (const float*)d_in[16];
    const float* Wv_add = (const float*)d_in[17];
    const float* bv_add = (const float*)d_in[18];
    const float* norm_added_q_w = (const float*)d_in[19];
    const float* norm_added_k_w = (const float*)d_in[20];
    const float* W_out = (const float*)d_in[21];
    const float* b_out = (const float*)d_in[22];
    const float* W_add_out = (const float*)d_in[23];
    const float* b_add_out = (const float*)d_in[24];
    const float* W_k_ip = (const float*)d_in[25];
    const float* b_k_ip = (const float*)d_in[26];
    const float* W_v_ip = (const float*)d_in[27];
    const float* b_v_ip = (const float*)d_in[28];
    const float* norm_ip_q_w = (const float*)d_in[29];
    const float* norm_ip_k_w = (const float*)d_in[30];

    float* out_img = (float*)d_out;
    float* out_enc = out_img + (size_t)IMG_ * HID_;

    float *q, *k, *v, *eq, *ek, *ev, *ipk, *ipv;
    float *qf, *kf, *vf, *ipq, *ipkh, *ipvh, *Sb, *Sip, *O, *ipO, *imgin, *encin;
    cudaGetSymbolAddress((void**)&q, g_q);
    cudaGetSymbolAddress((void**)&k, g_k);
    cudaGetSymbolAddress((void**)&v, g_v);
    cudaGetSymbolAddress((void**)&eq, g_eq);
    cudaGetSymbolAddress((void**)&ek, g_ek);
    cudaGetSymbolAddress((void**)&ev, g_ev);
    cudaGetSymbolAddress((void**)&ipk, g_ipk);
    cudaGetSymbolAddress((void**)&ipv, g_ipv);
    cudaGetSymbolAddress((void**)&qf, g_qf);
    cudaGetSymbolAddress((void**)&kf, g_kf);
    cudaGetSymbolAddress((void**)&vf, g_vf);
    cudaGetSymbolAddress((void**)&ipq, g_ipq);
    cudaGetSymbolAddress((void**)&ipkh, g_ipkh);
    cudaGetSymbolAddress((void**)&ipvh, g_ipvh);
    cudaGetSymbolAddress((void**)&Sb, g_S);
    cudaGetSymbolAddress((void**)&Sip, g_Sip);
    cudaGetSymbolAddress((void**)&O, g_O);
    cudaGetSymbolAddress((void**)&ipO, g_ipO);
    cudaGetSymbolAddress((void**)&imgin, g_imgin);
    cudaGetSymbolAddress((void**)&encin, g_encin);

    const float scale = 0.08838834764831845f; // 1/sqrt(128)

    // --- projections ---
    gemm_kernel<1><<<dim3(HID_ / 128, IMG_ / 128), 256>>>(hidden, Wq, bq, q, IMG_, HID_, HID_, 0, 0, 0);
    gemm_kernel<1><<<dim3(HID_ / 128, IMG_ / 128), 256>>>(hidden, Wk, bk, k, IMG_, HID_, HID_, 0, 0, 0);
    gemm_kernel<1><<<dim3(HID_ / 128, IMG_ / 128), 256>>>(hidden, Wv, bv, v, IMG_, HID_, HID_, 0, 0, 0);
    gemm_kernel<1><<<dim3(HID_ / 128, TXT_ / 128), 256>>>(enc_hs, Wq_add, bq_add, eq, TXT_, HID_, HID_, 0, 0, 0);
    gemm_kernel<1><<<dim3(HID_ / 128, TXT_ / 128), 256>>>(enc_hs, Wk_add, bk_add, ek, TXT_, HID_, HID_, 0, 0, 0);
    gemm_kernel<1><<<dim3(HID_ / 128, TXT_ / 128), 256>>>(enc_hs, Wv_add, bv_add, ev, TXT_, HID_, HID_, 0, 0, 0);
    gemm_kernel<1><<<dim3(HID_ / 128, IPL_ / 128), 256>>>(ip_hs, W_k_ip, b_k_ip, ipk, IPL_, HID_, IPD_, 0, 0, 0);
    gemm_kernel<1><<<dim3(HID_ / 128, IPL_ / 128), 256>>>(ip_hs, W_v_ip, b_v_ip, ipv, IPL_, HID_, IPD_, 0, 0, 0);

    // --- heads / rms / rope ---
    build_qk_rope<<<dim3(SALL, HN), 128>>>(eq, q, norm_added_q_w, norm_q_w, rope_cos, rope_sin, qf);
    build_qk_rope<<<dim3(SALL, HN), 128>>>(ek, k, norm_added_k_w, norm_k_w, rope_cos, rope_sin, kf);
    build_v_concat<<<dim3(SALL, HN), 128>>>(ev, v, vf);
    build_rms<<<dim3(IMG_, HN), 128>>>(q, norm_ip_q_w, ipq, IMG_);
    build_rms<<<dim3(IPL_, HN), 128>>>(ipk, norm_ip_k_w, ipkh, IPL_);
    build_heads<<<dim3(IPL_, HN), 128>>>(ipv, ipvh, IPL_);

    // --- main attention ---
    gemm_kernel<1><<<dim3(SALL / 128, SALL / 128, HN), 256>>>(
        qf, kf, nullptr, Sb, SALL, SALL, DHD,
        (long long)SALL * DHD, (long long)SALL * DHD, (long long)SALL * SALL);
    softmax_rows<<<HN * SALL, 256>>>(Sb, SALL, scale);
    gemm_kernel<0><<<dim3(1, SALL / 128, HN), 256>>>(
        Sb, vf, nullptr, O, SALL, DHD, SALL,
        (long long)SALL * SALL, (long long)SALL * DHD, (long long)SALL * DHD);

    // --- ip attention ---
    gemm_kernel<1><<<dim3(1, IMG_ / 128, HN), 256>>>(
        ipq, ipkh, nullptr, Sip, IMG_, IPL_, DHD,
        (long long)IMG_ * DHD, (long long)IPL_ * DHD, (long long)IMG_ * IPL_);
    softmax_rows<<<HN * IMG_, 256>>>(Sip, IPL_, scale);
    gemm_kernel<0><<<dim3(1, IMG_ / 128, HN), 256>>>(
        Sip, ipvh, nullptr, ipO, IMG_, DHD, IPL_,
        (long long)IMG_ * IPL_, (long long)IPL_ * DHD, (long long)IMG_ * DHD);

    // --- merge + output projections ---
    merge_img<<<dim3(IMG_, HN), 128>>>(O, ipO, imgin);
    merge_enc<<<dim3(TXT_, HN), 128>>>(O, encin);
    gemm_kernel<1><<<dim3(HID_ / 128, IMG_ / 128), 256>>>(imgin, W_out, b_out, out_img, IMG_, HID_, HID_, 0, 0, 0);
    gemm_kernel<1><<<dim3(HID_ / 128, TXT_ / 128), 256>>>(encin, W_add_out, b_add_out, out_enc, TXT_, HID_, HID_, 0, 0, 0);
}

// round 2
// speedup vs baseline: 1.2869x; 1.2869x over previous
#include <cuda_runtime.h>
#include <math.h>

#define HN   24
#define DHD  128
#define TXT_ 512
#define IMG_ 1024
#define SALL 1536
#define HID_ 3072
#define IPD_ 1152
#define IPL_ 128

// ---------------- static scratch (allocation-free) ----------------
__device__ float g_q[IMG_ * HID_];
__device__ float g_k[IMG_ * HID_];
__device__ float g_v[IMG_ * HID_];
__device__ float g_eq[TXT_ * HID_];
__device__ float g_ek[TXT_ * HID_];
__device__ float g_ev[TXT_ * HID_];
__device__ float g_ipk[IPL_ * HID_];
__device__ float g_ipv[IPL_ * HID_];
__device__ float g_qf[HN * SALL * DHD];
__device__ float g_kf[HN * SALL * DHD];
__device__ float g_vt[HN * DHD * SALL];     // V transposed per head: [h][d][s]
__device__ float g_ipq[HN * IMG_ * DHD];
__device__ float g_ipkh[HN * IPL_ * DHD];
__device__ float g_ipvt[HN * DHD * IPL_];   // ipV transposed per head
__device__ float g_S[HN * SALL * SALL];
__device__ float g_Sip[HN * IMG_ * IPL_];
__device__ float g_O[HN * SALL * DHD];
__device__ float g_ipO[HN * IMG_ * DHD];
__device__ float g_imgin[IMG_ * HID_];
__device__ float g_encin[TXT_ * HID_];

// ---------------- tf32 helpers ----------------
__device__ __forceinline__ unsigned f2tf(float x) {
    unsigned r;
    asm("cvt.rna.tf32.f32 %0, %1;" : "=r"(r) : "f"(x));
    return r;
}

__device__ __forceinline__ void mma_tf32(float* d, const unsigned* a, const unsigned* b) {
    asm volatile(
        "mma.sync.aligned.m16n8k8.row.col.f32.tf32.tf32.f32 "
        "{%0,%1,%2,%3}, {%4,%5,%6,%7}, {%8,%9}, {%0,%1,%2,%3};"
        : "+f"(d[0]), "+f"(d[1]), "+f"(d[2]), "+f"(d[3])
        : "r"(a[0]), "r"(a[1]), "r"(a[2]), "r"(a[3]), "r"(b[0]), "r"(b[1]));
}

// ---------------- tensor-core GEMM (NT): C[M,N] = A[M,K] * B[N,K]^T + bias ----
// BM=BN=128, BK=32, 256 threads (8 warps, 4x2). 3xTF32 precision split.
// Requires M%128==0, N%128==0, K%32==0.
__global__ __launch_bounds__(256) void gemm_tc(
    const float* __restrict__ A, const float* __restrict__ B,
    const float* __restrict__ bias, float* __restrict__ C,
    int M, int N, int K,
    long long sA, long long sB, long long sC)
{
    A += (long long)blockIdx.z * sA;
    B += (long long)blockIdx.z * sB;
    C += (long long)blockIdx.z * sC;

    __shared__ float As[128 * 32];
    __shared__ float Bs[128 * 32];

    int tid = threadIdx.x;
    int warp = tid >> 5, lane = tid & 31;
    int wm = warp >> 1, wn = warp & 1;
    int m0 = blockIdx.y * 128, n0 = blockIdx.x * 128;
    int r = lane >> 2, c = lane & 3;

    float acc[2][8][4];
#pragma unroll
    for (int mt = 0; mt < 2; mt++)
#pragma unroll
        for (int nt = 0; nt < 8; nt++)
#pragma unroll
            for (int i = 0; i < 4; i++) acc[mt][nt][i] = 0.f;

    int nkt = K >> 5;
    float4 pa[4], pb[4];

    // preload tile 0
#pragma unroll
    for (int it = 0; it < 4; it++) {
        int p = tid + it * 256;
        int row = p >> 3, kq = (p & 7) << 2;
        pa[it] = *(const float4*)(A + (long long)(m0 + row) * K + kq);
        pb[it] = *(const float4*)(B + (long long)(n0 + row) * K + kq);
    }
#pragma unroll
    for (int it = 0; it < 4; it++) {
        int p = tid + it * 256;
        int row = p >> 3, kq = (p & 7) << 2;
        int soff = row * 32 + (kq ^ ((row & 7) << 2));
        *(float4*)&As[soff] = pa[it];
        *(float4*)&Bs[soff] = pb[it];
    }
    __syncthreads();

    for (int kt = 0; kt < nkt; kt++) {
        if (kt + 1 < nkt) {
            int kbase = (kt + 1) << 5;
#pragma unroll
            for (int it = 0; it < 4; it++) {
                int p = tid + it * 256;
                int row = p >> 3, kq = (p & 7) << 2;
                pa[it] = *(const float4*)(A + (long long)(m0 + row) * K + kbase + kq);
                pb[it] = *(const float4*)(B + (long long)(n0 + row) * K + kbase + kq);
            }
        }

#pragma unroll
        for (int k8 = 0; k8 < 4; k8++) {
            unsigned ah[2][4], al[2][4];
#pragma unroll
            for (int mt = 0; mt < 2; mt++) {
                int mbase = wm * 32 + mt * 16;
#pragma unroll
                for (int i = 0; i < 4; i++) {
                    int mm = mbase + r + (i & 1) * 8;
                    int kk = k8 * 8 + c + (i >> 1) * 4;
                    float x = As[mm * 32 + (kk ^ ((mm & 7) << 2))];
                    unsigned h = f2tf(x);
                    ah[mt][i] = h;
                    al[mt][i] = f2tf(x - __uint_as_float(h));
                }
            }
#pragma unroll
            for (int nt = 0; nt < 8; nt++) {
                int nb = wn * 64 + nt * 8 + r;
                unsigned bh[2], bl[2];
#pragma unroll
                for (int i = 0; i < 2; i++) {
                    int kk = k8 * 8 + c + i * 4;
                    float x = Bs[nb * 32 + (kk ^ ((nb & 7) << 2))];
                    unsigned h = f2tf(x);
                    bh[i] = h;
                    bl[i] = f2tf(x - __uint_as_float(h));
                }
#pragma unroll
                for (int mt = 0; mt < 2; mt++) {
                    mma_tf32(acc[mt][nt], ah[mt], bh);
                    mma_tf32(acc[mt][nt], ah[mt], bl);
                    mma_tf32(acc[mt][nt], al[mt], bh);
                }
            }
        }
        __syncthreads();
        if (kt + 1 < nkt) {
#pragma unroll
            for (int it = 0; it < 4; it++) {
                int p = tid + it * 256;
                int row = p >> 3, kq = (p & 7) << 2;
                int soff = row * 32 + (kq ^ ((row & 7) << 2));
                *(float4*)&As[soff] = pa[it];
                *(float4*)&Bs[soff] = pb[it];
            }
            __syncthreads();
        }
    }

    // epilogue
#pragma unroll
    for (int nt = 0; nt < 8; nt++) {
        int ncol = n0 + wn * 64 + nt * 8 + c * 2;
        float2 bv;
        if (bias) bv = *(const float2*)(bias + ncol);
        else { bv.x = 0.f; bv.y = 0.f; }
#pragma unroll
        for (int mt = 0; mt < 2; mt++) {
            int mrow = m0 + wm * 32 + mt * 16 + r;
            float2 v0, v1;
            v0.x = acc[mt][nt][0] + bv.x; v0.y = acc[mt][nt][1] + bv.y;
            v1.x = acc[mt][nt][2] + bv.x; v1.y = acc[mt][nt][3] + bv.y;
            *(float2*)(C + (long long)mrow * N + ncol) = v0;
            *(float2*)(C + (long long)(mrow + 8) * N + ncol) = v1;
        }
    }
}

// ---------------- heads + RMS + RoPE (concat enc/img) ----------------
__global__ void build_qk_rope(const float* __restrict__ enc_lin,
                              const float* __restrict__ img_lin,
                              const float* __restrict__ w_enc,
                              const float* __restrict__ w_img,
                              const float* __restrict__ cosb,
                              const float* __restrict__ sinb,
                              float* __restrict__ dst)
{
    int s = blockIdx.x;
    int h = blockIdx.y;
    int d = threadIdx.x;
    const float* src;
    const float* w;
    if (s < TXT_) { src = enc_lin + (long long)s * HID_; w = w_enc; }
    else          { src = img_lin + (long long)(s - TXT_) * HID_; w = w_img; }
    float x = src[h * DHD + d];
    float ss = x * x;
#pragma unroll
    for (int o = 16; o; o >>= 1) ss += __shfl_xor_sync(0xffffffffu, ss, o);
    __shared__ float sred[4];
    int lane = d & 31, wid = d >> 5;
    if (lane == 0) sred[wid] = ss;
    __syncthreads();
    ss = sred[0] + sred[1] + sred[2] + sred[3];
    float r = rsqrtf(ss * (1.0f / DHD) + 1e-6f);
    float xn = x * r * w[d];
    float partner = __shfl_xor_sync(0xffffffffu, xn, 1);
    float rot = (d & 1) ? partner : -partner;
    long long si = (long long)s * DHD + d;
    dst[((long long)h * SALL + s) * DHD + d] = xn * cosb[si] + rot * sinb[si];
}

// dst[h][s][d] = rms(src[s, h*128+d]) * w[d]
__global__ void build_rms(const float* __restrict__ src, const float* __restrict__ w,
                          float* __restrict__ dst, int Srows)
{
    int s = blockIdx.x;
    int h = blockIdx.y;
    int d = threadIdx.x;
    float x = src[(long long)s * HID_ + h * DHD + d];
    float ss = x * x;
#pragma unroll
    for (int o = 16; o; o >>= 1) ss += __shfl_xor_sync(0xffffffffu, ss, o);
    __shared__ float sred[4];
    int lane = d & 31, wid = d >> 5;
    if (lane == 0) sred[wid] = ss;
    __syncthreads();
    ss = sred[0] + sred[1] + sred[2] + sred[3];
    float r = rsqrtf(ss * (1.0f / DHD) + 1e-6f);
    dst[((long long)h * Srows + s) * DHD + d] = x * r * w[d];
}

// Transposed heads: dst[h][d][s] from enc/img concat. block (32,8), grid (S/32, 4, HN)
__global__ void transpose_heads(const float* __restrict__ enc, const float* __restrict__ img,
                                int ntxt, float* __restrict__ dst, int Srows)
{
    __shared__ float t[32][33];
    int s0 = blockIdx.x * 32, d0 = blockIdx.y * 32, h = blockIdx.z;
    int tx = threadIdx.x, ty = threadIdx.y;
#pragma unroll
    for (int j = 0; j < 4; j++) {
        int s = s0 + ty + j * 8;
        const float* src = (s < ntxt) ? enc + (long long)s * HID_
                                      : img + (long long)(s - ntxt) * HID_;
        t[ty + j * 8][tx] = src[h * DHD + d0 + tx];
    }
    __syncthreads();
#pragma unroll
    for (int j = 0; j < 4; j++) {
        int d = d0 + ty + j * 8;
        dst[((long long)h * DHD + d) * Srows + s0 + tx] = t[tx][ty + j * 8];
    }
}

// ---------------- softmax over rows ----------------
__global__ void softmax_rows(float* __restrict__ S, int ncols, float scale)
{
    long long row = blockIdx.x;
    float* p = S + row * (long long)ncols;
    int tid = threadIdx.x;
    float lv[6];
    int cnt = 0;
    float mx = -INFINITY;
    for (int j = tid; j < ncols; j += 256) {
        float v = p[j] * scale;
        lv[cnt++] = v;
        mx = fmaxf(mx, v);
    }
    __shared__ float sred[8];
    int lane = tid & 31, wid = tid >> 5;
#pragma unroll
    for (int o = 16; o; o >>= 1) mx = fmaxf(mx, __shfl_xor_sync(0xffffffffu, mx, o));
    if (lane == 0) sred[wid] = mx;
    __syncthreads();
    mx = sred[0];
#pragma unroll
    for (int i = 1; i < 8; i++) mx = fmaxf(mx, sred[i]);
    __syncthreads();
    float sum = 0.f;
    for (int c = 0; c < cnt; c++) {
        float e = expf(lv[c] - mx);
        lv[c] = e;
        sum += e;
    }
#pragma unroll
    for (int o = 16; o; o >>= 1) sum += __shfl_xor_sync(0xffffffffu, sum, o);
    if (lane == 0) sred[wid] = sum;
    __syncthreads();
    sum = sred[0];
#pragma unroll
    for (int i = 1; i < 8; i++) sum += sred[i];
    float inv = 1.0f / sum;
    cnt = 0;
    for (int j = tid; j < ncols; j += 256) p[j] = lv[cnt++] * inv;
}

// ---------------- merge + bbox mask ----------------
__global__ void merge_img(const float* __restrict__ O, const float* __restrict__ ipO,
                          float* __restrict__ dst)
{
    int l = blockIdx.x, h = blockIdx.y, d = threadIdx.x;
    int row = l >> 5, col = l & 31;
    float m = (row >= 8 && row < 24 && col >= 8 && col < 24) ? 1.0f : 0.0f;
    dst[(long long)l * HID_ + h * DHD + d] =
        O[((long long)h * SALL + TXT_ + l) * DHD + d] +
        m * ipO[((long long)h * IMG_ + l) * DHD + d];
}

__global__ void merge_enc(const float* __restrict__ O, float* __restrict__ dst)
{
    int s = blockIdx.x, h = blockIdx.y, d = threadIdx.x;
    dst[(long long)s * HID_ + h * DHD + d] = O[((long long)h * SALL + s) * DHD + d];
}

// ---------------- launch ----------------
extern "C" void kernel_launch(void* const* d_in, const int* in_sizes, int n_in,
                              void* d_out, int out_size)
{
    const float* hidden   = (const float*)d_in[0];
    const float* enc_hs   = (const float*)d_in[1];
    const float* ip_hs    = (const float*)d_in[2];
    const float* rope_cos = (const float*)d_in[3];
    const float* rope_sin = (const float*)d_in[4];
    const float* Wq  = (const float*)d_in[5];
    const float* bq  = (const float*)d_in[6];
    const float* Wk  = (const float*)d_in[7];
    const float* bk  = (const float*)d_in[8];
    const float* Wv  = (const float*)d_in[9];
    const float* bv  = (const float*)d_in[10];
    const float* norm_q_w = (const float*)d_in[11];
    const float* norm_k_w = (const float*)d_in[12];
    const float* Wq_add = (const float*)d_in[13];
    const float* bq_add = (const float*)d_in[14];
    const float* Wk_add = (const float*)d_in[15];
    const float* bk_add = (const float*)d_in[16];
    const float* Wv_add = (const float*)d_in[17];
    const float* bv_add = (const float*)d_in[18];
    const float* norm_added_q_w = (const float*)d_in[19];
    const float* norm_added_k_w = (const float*)d_in[20];
    const float* W_out = (const float*)d_in[21];
    const float* b_out = (const float*)d_in[22];
    const float* W_add_out = (const float*)d_in[23];
    const float* b_add_out = (const float*)d_in[24];
    const float* W_k_ip = (const float*)d_in[25];
    const float* b_k_ip = (const float*)d_in[26];
    const float* W_v_ip = (const float*)d_in[27];
    const float* b_v_ip = (const float*)d_in[28];
    const float* norm_ip_q_w = (const float*)d_in[29];
    const float* norm_ip_k_w = (const float*)d_in[30];

    float* out_img = (float*)d_out;
    float* out_enc = out_img + (size_t)IMG_ * HID_;

    float *q, *k, *v, *eq, *ek, *ev, *ipk, *ipv;
    float *qf, *kf, *vt, *ipq, *ipkh, *ipvt, *Sb, *Sip, *O, *ipO, *imgin, *encin;
    cudaGetSymbolAddress((void**)&q, g_q);
    cudaGetSymbolAddress((void**)&k, g_k);
    cudaGetSymbolAddress((void**)&v, g_v);
    cudaGetSymbolAddress((void**)&eq, g_eq);
    cudaGetSymbolAddress((void**)&ek, g_ek);
    cudaGetSymbolAddress((void**)&ev, g_ev);
    cudaGetSymbolAddress((void**)&ipk, g_ipk);
    cudaGetSymbolAddress((void**)&ipv, g_ipv);
    cudaGetSymbolAddress((void**)&qf, g_qf);
    cudaGetSymbolAddress((void**)&kf, g_kf);
    cudaGetSymbolAddress((void**)&vt, g_vt);
    cudaGetSymbolAddress((void**)&ipq, g_ipq);
    cudaGetSymbolAddress((void**)&ipkh, g_ipkh);
    cudaGetSymbolAddress((void**)&ipvt, g_ipvt);
    cudaGetSymbolAddress((void**)&Sb, g_S);
    cudaGetSymbolAddress((void**)&Sip, g_Sip);
    cudaGetSymbolAddress((void**)&O, g_O);
    cudaGetSymbolAddress((void**)&ipO, g_ipO);
    cudaGetSymbolAddress((void**)&imgin, g_imgin);
    cudaGetSymbolAddress((void**)&encin, g_encin);

    const float scale = 0.08838834764831845f; // 1/sqrt(128)

    // --- projections (tensor-core, 3xTF32) ---
    gemm_tc<<<dim3(HID_ / 128, IMG_ / 128), 256>>>(hidden, Wq, bq, q, IMG_, HID_, HID_, 0, 0, 0);
    gemm_tc<<<dim3(HID_ / 128, IMG_ / 128), 256>>>(hidden, Wk, bk, k, IMG_, HID_, HID_, 0, 0, 0);
    gemm_tc<<<dim3(HID_ / 128, IMG_ / 128), 256>>>(hidden, Wv, bv, v, IMG_, HID_, HID_, 0, 0, 0);
    gemm_tc<<<dim3(HID_ / 128, TXT_ / 128), 256>>>(enc_hs, Wq_add, bq_add, eq, TXT_, HID_, HID_, 0, 0, 0);
    gemm_tc<<<dim3(HID_ / 128, TXT_ / 128), 256>>>(enc_hs, Wk_add, bk_add, ek, TXT_, HID_, HID_, 0, 0, 0);
    gemm_tc<<<dim3(HID_ / 128, TXT_ / 128), 256>>>(enc_hs, Wv_add, bv_add, ev, TXT_, HID_, HID_, 0, 0, 0);
    gemm_tc<<<dim3(HID_ / 128, IPL_ / 128), 256>>>(ip_hs, W_k_ip, b_k_ip, ipk, IPL_, HID_, IPD_, 0, 0, 0);
    gemm_tc<<<dim3(HID_ / 128, IPL_ / 128), 256>>>(ip_hs, W_v_ip, b_v_ip, ipv, IPL_, HID_, IPD_, 0, 0, 0);

    // --- heads / rms / rope / transposes ---
    build_qk_rope<<<dim3(SALL, HN), 128>>>(eq, q, norm_added_q_w, norm_q_w, rope_cos, rope_sin, qf);
    build_qk_rope<<<dim3(SALL, HN), 128>>>(ek, k, norm_added_k_w, norm_k_w, rope_cos, rope_sin, kf);
    transpose_heads<<<dim3(SALL / 32, DHD / 32, HN), dim3(32, 8)>>>(ev, v, TXT_, vt, SALL);
    build_rms<<<dim3(IMG_, HN), 128>>>(q, norm_ip_q_w, ipq, IMG_);
    build_rms<<<dim3(IPL_, HN), 128>>>(ipk, norm_ip_k_w, ipkh, IPL_);
    transpose_heads<<<dim3(IPL_ / 32, DHD / 32, HN), dim3(32, 8)>>>(ipv, ipv, IPL_, ipvt, IPL_);

    // --- main attention ---
    gemm_tc<<<dim3(SALL / 128, SALL / 128, HN), 256>>>(
        qf, kf, nullptr, Sb, SALL, SALL, DHD,
        (long long)SALL * DHD, (long long)SALL * DHD, (long long)SALL * SALL);
    softmax_rows<<<HN * SALL, 256>>>(Sb, SALL, scale);
    gemm_tc<<<dim3(1, SALL / 128, HN), 256>>>(
        Sb, vt, nullptr, O, SALL, DHD, SALL,
        (long long)SALL * SALL, (long long)DHD * SALL, (long long)SALL * DHD);

    // --- ip attention ---
    gemm_tc<<<dim3(1, IMG_ / 128, HN), 256>>>(
        ipq, ipkh, nullptr, Sip, IMG_, IPL_, DHD,
        (long long)IMG_ * DHD, (long long)IPL_ * DHD, (long long)IMG_ * IPL_);
    softmax_rows<<<HN * IMG_, 256>>>(Sip, IPL_, scale);
    gemm_tc<<<dim3(1, IMG_ / 128, HN), 256>>>(
        Sip, ipvt, nullptr, ipO, IMG_, DHD, IPL_,
        (long long)IMG_ * IPL_, (long long)DHD * IPL_, (long long)IMG_ * DHD);

    // --- merge + output projections ---
    merge_img<<<dim3(IMG_, HN), 128>>>(O, ipO, imgin);
    merge_enc<<<dim3(TXT_, HN), 128>>>(O, encin);
    gemm_tc<<<dim3(HID_ / 128, IMG_ / 128), 256>>>(imgin, W_out, b_out, out_img, IMG_, HID_, HID_, 0, 0, 0);
    gemm_tc<<<dim3(HID_ / 128, TXT_ / 128), 256>>>(encin, W_add_out, b_add_out, out_enc, TXT_, HID_, HID_, 0, 0, 0);
}

// round 3
// speedup vs baseline: 1.8028x; 1.4008x over previous
#include <cuda_runtime.h>
#include <cuda_bf16.h>
#include <math.h>

#define HN   24
#define DHD  128
#define TXT_ 512
#define IMG_ 1024
#define SALL 1536
#define HID_ 3072
#define IPD_ 1152
#define IPL_ 128

// ---------------- static scratch (allocation-free) ----------------
__device__ float g_q[IMG_ * HID_];
__device__ float g_k[IMG_ * HID_];
__device__ float g_v[IMG_ * HID_];
__device__ float g_eq[TXT_ * HID_];
__device__ float g_ek[TXT_ * HID_];
__device__ float g_ev[TXT_ * HID_];
__device__ float g_ipk[IPL_ * HID_];
__device__ float g_ipv[IPL_ * HID_];
__device__ float g_qf[HN * SALL * DHD];
__device__ float g_kf[HN * SALL * DHD];
__device__ float g_vt[HN * DHD * SALL];
__device__ float g_ipq[HN * IMG_ * DHD];
__device__ float g_ipkh[HN * IPL_ * DHD];
__device__ float g_ipvt[HN * DHD * IPL_];
__device__ float g_S[HN * SALL * SALL];
__device__ float g_Sip[HN * IMG_ * IPL_];
__device__ float g_O[HN * SALL * DHD];
__device__ float g_ipO[HN * IMG_ * DHD];
__device__ float g_imgin[IMG_ * HID_];
__device__ float g_encin[TXT_ * HID_];

// ---------------- bf16 hi/lo split helpers ----------------
__device__ __forceinline__ uint2 pack2(float f0, float f1) {
    __nv_bfloat16 h0 = __float2bfloat16(f0);
    __nv_bfloat16 h1 = __float2bfloat16(f1);
    __nv_bfloat16 l0 = __float2bfloat16(f0 - __bfloat162float(h0));
    __nv_bfloat16 l1 = __float2bfloat16(f1 - __bfloat162float(h1));
    uint2 u;
    u.x = (unsigned)__bfloat16_as_ushort(h0) | ((unsigned)__bfloat16_as_ushort(h1) << 16);
    u.y = (unsigned)__bfloat16_as_ushort(l0) | ((unsigned)__bfloat16_as_ushort(l1) << 16);
    return u;
}

__device__ __forceinline__ void mma_bf16(float* d, const unsigned* a, const unsigned* b) {
    asm volatile(
        "mma.sync.aligned.m16n8k16.row.col.f32.bf16.bf16.f32 "
        "{%0,%1,%2,%3}, {%4,%5,%6,%7}, {%8,%9}, {%0,%1,%2,%3};"
        : "+f"(d[0]), "+f"(d[1]), "+f"(d[2]), "+f"(d[3])
        : "r"(a[0]), "r"(a[1]), "r"(a[2]), "r"(a[3]), "r"(b[0]), "r"(b[1]));
}

// smem pair index with xor swizzle: row r, pair e (0..15) of 8B elements
__device__ __forceinline__ int sidx(int r, int e) {
    return r * 16 + (e ^ ((r & 3) << 2));
}

// ---------------- bf16x3 tensor-core GEMM (NT): C = A[M,K] * B[N,K]^T + bias --
// BM=128, BN=64, BK=32, 256 threads (8 warps 4x2). Requires M%128, N%64, K%32.
__global__ __launch_bounds__(256, 2) void gemm_tc(
    const float* __restrict__ A, const float* __restrict__ B,
    const float* __restrict__ bias, float* __restrict__ C,
    int M, int N, int K,
    long long sA, long long sB, long long sC)
{
    A += (long long)blockIdx.z * sA;
    B += (long long)blockIdx.z * sB;
    C += (long long)blockIdx.z * sC;

    __shared__ uint2 As[128 * 16];   // 16 KB
    __shared__ uint2 Bs[64 * 16];    // 8 KB

    int tid = threadIdx.x;
    int warp = tid >> 5, lane = tid & 31;
    int wm = warp >> 1, wn = warp & 1;
    int m0 = blockIdx.y * 128, n0 = blockIdx.x * 64;
    int g = lane >> 2, t = lane & 3;

    float acc[2][4][4];
#pragma unroll
    for (int mt = 0; mt < 2; mt++)
#pragma unroll
        for (int nt = 0; nt < 4; nt++)
#pragma unroll
            for (int i = 0; i < 4; i++) acc[mt][nt][i] = 0.f;

    int nkt = K >> 5;
    float4 pa[4], pb[2];

    // preload k-tile 0
#pragma unroll
    for (int it = 0; it < 4; it++) {
        int p = tid + it * 256;
        int row = p >> 3, q = p & 7;
        pa[it] = *(const float4*)(A + (long long)(m0 + row) * K + q * 4);
    }
#pragma unroll
    for (int it = 0; it < 2; it++) {
        int p = tid + it * 256;
        int row = p >> 3, q = p & 7;
        pb[it] = *(const float4*)(B + (long long)(n0 + row) * K + q * 4);
    }
#pragma unroll
    for (int it = 0; it < 4; it++) {
        int p = tid + it * 256;
        int row = p >> 3, q = p & 7;
        As[sidx(row, 2 * q)]     = pack2(pa[it].x, pa[it].y);
        As[sidx(row, 2 * q + 1)] = pack2(pa[it].z, pa[it].w);
    }
#pragma unroll
    for (int it = 0; it < 2; it++) {
        int p = tid + it * 256;
        int row = p >> 3, q = p & 7;
        Bs[sidx(row, 2 * q)]     = pack2(pb[it].x, pb[it].y);
        Bs[sidx(row, 2 * q + 1)] = pack2(pb[it].z, pb[it].w);
    }
    __syncthreads();

    for (int kt = 0; kt < nkt; kt++) {
        if (kt + 1 < nkt) {
            int kb = (kt + 1) << 5;
#pragma unroll
            for (int it = 0; it < 4; it++) {
                int p = tid + it * 256;
                int row = p >> 3, q = p & 7;
                pa[it] = *(const float4*)(A + (long long)(m0 + row) * K + kb + q * 4);
            }
#pragma unroll
            for (int it = 0; it < 2; it++) {
                int p = tid + it * 256;
                int row = p >> 3, q = p & 7;
                pb[it] = *(const float4*)(B + (long long)(n0 + row) * K + kb + q * 4);
            }
        }

#pragma unroll
        for (int kc = 0; kc < 2; kc++) {
            unsigned ah[2][4], al[2][4];
#pragma unroll
            for (int mt = 0; mt < 2; mt++) {
                int mr = wm * 32 + mt * 16 + g;
                int e0 = kc * 8 + t;
                uint2 u0 = As[sidx(mr, e0)];
                uint2 u1 = As[sidx(mr + 8, e0)];
                uint2 u2 = As[sidx(mr, e0 + 4)];
                uint2 u3 = As[sidx(mr + 8, e0 + 4)];
                ah[mt][0] = u0.x; al[mt][0] = u0.y;
                ah[mt][1] = u1.x; al[mt][1] = u1.y;
                ah[mt][2] = u2.x; al[mt][2] = u2.y;
                ah[mt][3] = u3.x; al[mt][3] = u3.y;
            }
#pragma unroll
            for (int nt = 0; nt < 4; nt++) {
                int nr = wn * 32 + nt * 8 + g;
                int e0 = kc * 8 + t;
                uint2 v0 = Bs[sidx(nr, e0)];
                uint2 v1 = Bs[sidx(nr, e0 + 4)];
                unsigned bh[2] = { v0.x, v1.x };
                unsigned bl[2] = { v0.y, v1.y };
#pragma unroll
                for (int mt = 0; mt < 2; mt++) {
                    mma_bf16(acc[mt][nt], ah[mt], bh);
                    mma_bf16(acc[mt][nt], ah[mt], bl);
                    mma_bf16(acc[mt][nt], al[mt], bh);
                }
            }
        }
        __syncthreads();
        if (kt + 1 < nkt) {
#pragma unroll
            for (int it = 0; it < 4; it++) {
                int p = tid + it * 256;
                int row = p >> 3, q = p & 7;
                As[sidx(row, 2 * q)]     = pack2(pa[it].x, pa[it].y);
                As[sidx(row, 2 * q + 1)] = pack2(pa[it].z, pa[it].w);
            }
#pragma unroll
            for (int it = 0; it < 2; it++) {
                int p = tid + it * 256;
                int row = p >> 3, q = p & 7;
                Bs[sidx(row, 2 * q)]     = pack2(pb[it].x, pb[it].y);
                Bs[sidx(row, 2 * q + 1)] = pack2(pb[it].z, pb[it].w);
            }
            __syncthreads();
        }
    }

    // epilogue: c0,c1 -> (row g, cols 2t,2t+1), c2,c3 -> row g+8
#pragma unroll
    for (int nt = 0; nt < 4; nt++) {
        int ncol = n0 + wn * 32 + nt * 8 + t * 2;
        float2 bv;
        if (bias) bv = *(const float2*)(bias + ncol);
        else { bv.x = 0.f; bv.y = 0.f; }
#pragma unroll
        for (int mt = 0; mt < 2; mt++) {
            int mrow = m0 + wm * 32 + mt * 16 + g;
            float2 v0, v1;
            v0.x = acc[mt][nt][0] + bv.x; v0.y = acc[mt][nt][1] + bv.y;
            v1.x = acc[mt][nt][2] + bv.x; v1.y = acc[mt][nt][3] + bv.y;
            *(float2*)(C + (long long)mrow * N + ncol) = v0;
            *(float2*)(C + (long long)(mrow + 8) * N + ncol) = v1;
        }
    }
}

// ---------------- heads + RMS + RoPE (concat enc/img) ----------------
__global__ void build_qk_rope(const float* __restrict__ enc_lin,
                              const float* __restrict__ img_lin,
                              const float* __restrict__ w_enc,
                              const float* __restrict__ w_img,
                              const float* __restrict__ cosb,
                              const float* __restrict__ sinb,
                              float* __restrict__ dst)
{
    int s = blockIdx.x;
    int h = blockIdx.y;
    int d = threadIdx.x;
    const float* src;
    const float* w;
    if (s < TXT_) { src = enc_lin + (long long)s * HID_; w = w_enc; }
    else          { src = img_lin + (long long)(s - TXT_) * HID_; w = w_img; }
    float x = src[h * DHD + d];
    float ss = x * x;
#pragma unroll
    for (int o = 16; o; o >>= 1) ss += __shfl_xor_sync(0xffffffffu, ss, o);
    __shared__ float sred[4];
    int lane = d & 31, wid = d >> 5;
    if (lane == 0) sred[wid] = ss;
    __syncthreads();
    ss = sred[0] + sred[1] + sred[2] + sred[3];
    float r = rsqrtf(ss * (1.0f / DHD) + 1e-6f);
    float xn = x * r * w[d];
    float partner = __shfl_xor_sync(0xffffffffu, xn, 1);
    float rot = (d & 1) ? partner : -partner;
    long long si = (long long)s * DHD + d;
    dst[((long long)h * SALL + s) * DHD + d] = xn * cosb[si] + rot * sinb[si];
}

__global__ void build_rms(const float* __restrict__ src, const float* __restrict__ w,
                          float* __restrict__ dst, int Srows)
{
    int s = blockIdx.x;
    int h = blockIdx.y;
    int d = threadIdx.x;
    float x = src[(long long)s * HID_ + h * DHD + d];
    float ss = x * x;
#pragma unroll
    for (int o = 16; o; o >>= 1) ss += __shfl_xor_sync(0xffffffffu, ss, o);
    __shared__ float sred[4];
    int lane = d & 31, wid = d >> 5;
    if (lane == 0) sred[wid] = ss;
    __syncthreads();
    ss = sred[0] + sred[1] + sred[2] + sred[3];
    float r = rsqrtf(ss * (1.0f / DHD) + 1e-6f);
    dst[((long long)h * Srows + s) * DHD + d] = x * r * w[d];
}

// dst[h][d][s] from enc/img concat. block (32,8), grid (S/32, 4, HN)
__global__ void transpose_heads(const float* __restrict__ enc, const float* __restrict__ img,
                                int ntxt, float* __restrict__ dst, int Srows)
{
    __shared__ float tbuf[32][33];
    int s0 = blockIdx.x * 32, d0 = blockIdx.y * 32, h = blockIdx.z;
    int tx = threadIdx.x, ty = threadIdx.y;
#pragma unroll
    for (int j = 0; j < 4; j++) {
        int s = s0 + ty + j * 8;
        const float* src = (s < ntxt) ? enc + (long long)s * HID_
                                      : img + (long long)(s - ntxt) * HID_;
        tbuf[ty + j * 8][tx] = src[h * DHD + d0 + tx];
    }
    __syncthreads();
#pragma unroll
    for (int j = 0; j < 4; j++) {
        int d = d0 + ty + j * 8;
        dst[((long long)h * DHD + d) * Srows + s0 + tx] = tbuf[tx][ty + j * 8];
    }
}

// ---------------- softmax over rows ----------------
__global__ void softmax_rows(float* __restrict__ S, int ncols, float scale)
{
    long long row = blockIdx.x;
    float* p = S + row * (long long)ncols;
    int tid = threadIdx.x;
    float lv[6];
    int cnt = 0;
    float mx = -INFINITY;
    for (int j = tid; j < ncols; j += 256) {
        float v = p[j] * scale;
        lv[cnt++] = v;
        mx = fmaxf(mx, v);
    }
    __shared__ float sred[8];
    int lane = tid & 31, wid = tid >> 5;
#pragma unroll
    for (int o = 16; o; o >>= 1) mx = fmaxf(mx, __shfl_xor_sync(0xffffffffu, mx, o));
    if (lane == 0) sred[wid] = mx;
    __syncthreads();
    mx = sred[0];
#pragma unroll
    for (int i = 1; i < 8; i++) mx = fmaxf(mx, sred[i]);
    __syncthreads();
    float sum = 0.f;
    for (int c = 0; c < cnt; c++) {
        float e = expf(lv[c] - mx);
        lv[c] = e;
        sum += e;
    }
#pragma unroll
    for (int o = 16; o; o >>= 1) sum += __shfl_xor_sync(0xffffffffu, sum, o);
    if (lane == 0) sred[wid] = sum;
    __syncthreads();
    sum = sred[0];
#pragma unroll
    for (int i = 1; i < 8; i++) sum += sred[i];
    float inv = 1.0f / sum;
    cnt = 0;
    for (int j = tid; j < ncols; j += 256) p[j] = lv[cnt++] * inv;
}

// ---------------- merge + bbox mask ----------------
__global__ void merge_img(const float* __restrict__ O, const float* __restrict__ ipO,
                          float* __restrict__ dst)
{
    int l = blockIdx.x, h = blockIdx.y, d = threadIdx.x;
    int row = l >> 5, col = l & 31;
    float m = (row >= 8 && row < 24 && col >= 8 && col < 24) ? 1.0f : 0.0f;
    dst[(long long)l * HID_ + h * DHD + d] =
        O[((long long)h * SALL + TXT_ + l) * DHD + d] +
        m * ipO[((long long)h * IMG_ + l) * DHD + d];
}

__global__ void merge_enc(const float* __restrict__ O, float* __restrict__ dst)
{
    int s = blockIdx.x, h = blockIdx.y, d = threadIdx.x;
    dst[(long long)s * HID_ + h * DHD + d] = O[((long long)h * SALL + s) * DHD + d];
}

// ---------------- launch ----------------
extern "C" void kernel_launch(void* const* d_in, const int* in_sizes, int n_in,
                              void* d_out, int out_size)
{
    const float* hidden   = (const float*)d_in[0];
    const float* enc_hs   = (const float*)d_in[1];
    const float* ip_hs    = (const float*)d_in[2];
    const float* rope_cos = (const float*)d_in[3];
    const float* rope_sin = (const float*)d_in[4];
    const float* Wq  = (const float*)d_in[5];
    const float* bq  = (const float*)d_in[6];
    const float* Wk  = (const float*)d_in[7];
    const float* bk  = (const float*)d_in[8];
    const float* Wv  = (const float*)d_in[9];
    const float* bv  = (const float*)d_in[10];
    const float* norm_q_w = (const float*)d_in[11];
    const float* norm_k_w = (const float*)d_in[12];
    const float* Wq_add = (const float*)d_in[13];
    const float* bq_add = (const float*)d_in[14];
    const float* Wk_add = (const float*)d_in[15];
    const float* bk_add = (const float*)d_in[16];
    const float* Wv_add = (const float*)d_in[17];
    const float* bv_add = (const float*)d_in[18];
    const float* norm_added_q_w = (const float*)d_in[19];
    const float* norm_added_k_w = (const float*)d_in[20];
    const float* W_out = (const float*)d_in[21];
    const float* b_out = (const float*)d_in[22];
    const float* W_add_out = (const float*)d_in[23];
    const float* b_add_out = (const float*)d_in[24];
    const float* W_k_ip = (const float*)d_in[25];
    const float* b_k_ip = (const float*)d_in[26];
    const float* W_v_ip = (const float*)d_in[27];
    const float* b_v_ip = (const float*)d_in[28];
    const float* norm_ip_q_w = (const float*)d_in[29];
    const float* norm_ip_k_w = (const float*)d_in[30];

    float* out_img = (float*)d_out;
    float* out_enc = out_img + (size_t)IMG_ * HID_;

    float *q, *k, *v, *eq, *ek, *ev, *ipk, *ipv;
    float *qf, *kf, *vt, *ipq, *ipkh, *ipvt, *Sb, *Sip, *O, *ipO, *imgin, *encin;
    cudaGetSymbolAddress((void**)&q, g_q);
    cudaGetSymbolAddress((void**)&k, g_k);
    cudaGetSymbolAddress((void**)&v, g_v);
    cudaGetSymbolAddress((void**)&eq, g_eq);
    cudaGetSymbolAddress((void**)&ek, g_ek);
    cudaGetSymbolAddress((void**)&ev, g_ev);
    cudaGetSymbolAddress((void**)&ipk, g_ipk);
    cudaGetSymbolAddress((void**)&ipv, g_ipv);
    cudaGetSymbolAddress((void**)&qf, g_qf);
    cudaGetSymbolAddress((void**)&kf, g_kf);
    cudaGetSymbolAddress((void**)&vt, g_vt);
    cudaGetSymbolAddress((void**)&ipq, g_ipq);
    cudaGetSymbolAddress((void**)&ipkh, g_ipkh);
    cudaGetSymbolAddress((void**)&ipvt, g_ipvt);
    cudaGetSymbolAddress((void**)&Sb, g_S);
    cudaGetSymbolAddress((void**)&Sip, g_Sip);
    cudaGetSymbolAddress((void**)&O, g_O);
    cudaGetSymbolAddress((void**)&ipO, g_ipO);
    cudaGetSymbolAddress((void**)&imgin, g_imgin);
    cudaGetSymbolAddress((void**)&encin, g_encin);

    const float scale = 0.08838834764831845f; // 1/sqrt(128)

    // --- projections (bf16x3 tensor-core) ---
    gemm_tc<<<dim3(HID_ / 64, IMG_ / 128), 256>>>(hidden, Wq, bq, q, IMG_, HID_, HID_, 0, 0, 0);
    gemm_tc<<<dim3(HID_ / 64, IMG_ / 128), 256>>>(hidden, Wk, bk, k, IMG_, HID_, HID_, 0, 0, 0);
    gemm_tc<<<dim3(HID_ / 64, IMG_ / 128), 256>>>(hidden, Wv, bv, v, IMG_, HID_, HID_, 0, 0, 0);
    gemm_tc<<<dim3(HID_ / 64, TXT_ / 128), 256>>>(enc_hs, Wq_add, bq_add, eq, TXT_, HID_, HID_, 0, 0, 0);
    gemm_tc<<<dim3(HID_ / 64, TXT_ / 128), 256>>>(enc_hs, Wk_add, bk_add, ek, TXT_, HID_, HID_, 0, 0, 0);
    gemm_tc<<<dim3(HID_ / 64, TXT_ / 128), 256>>>(enc_hs, Wv_add, bv_add, ev, TXT_, HID_, HID_, 0, 0, 0);
    gemm_tc<<<dim3(HID_ / 64, IPL_ / 128), 256>>>(ip_hs, W_k_ip, b_k_ip, ipk, IPL_, HID_, IPD_, 0, 0, 0);
    gemm_tc<<<dim3(HID_ / 64, IPL_ / 128), 256>>>(ip_hs, W_v_ip, b_v_ip, ipv, IPL_, HID_, IPD_, 0, 0, 0);

    // --- heads / rms / rope / transposes ---
    build_qk_rope<<<dim3(SALL, HN), 128>>>(eq, q, norm_added_q_w, norm_q_w, rope_cos, rope_sin, qf);
    build_qk_rope<<<dim3(SALL, HN), 128>>>(ek, k, norm_added_k_w, norm_k_w, rope_cos, rope_sin, kf);
    transpose_heads<<<dim3(SALL / 32, DHD / 32, HN), dim3(32, 8)>>>(ev, v, TXT_, vt, SALL);
    build_rms<<<dim3(IMG_, HN), 128>>>(q, norm_ip_q_w, ipq, IMG_);
    build_rms<<<dim3(IPL_, HN), 128>>>(ipk, norm_ip_k_w, ipkh, IPL_);
    transpose_heads<<<dim3(IPL_ / 32, DHD / 32, HN), dim3(32, 8)>>>(ipv, ipv, IPL_, ipvt, IPL_);

    // --- main attention ---
    gemm_tc<<<dim3(SALL / 64, SALL / 128, HN), 256>>>(
        qf, kf, nullptr, Sb, SALL, SALL, DHD,
        (long long)SALL * DHD, (long long)SALL * DHD, (long long)SALL * SALL);
    softmax_rows<<<HN * SALL, 256>>>(Sb, SALL, scale);
    gemm_tc<<<dim3(DHD / 64, SALL / 128, HN), 256>>>(
        Sb, vt, nullptr, O, SALL, DHD, SALL,
        (long long)SALL * SALL, (long long)DHD * SALL, (long long)SALL * DHD);

    // --- ip attention ---
    gemm_tc<<<dim3(IPL_ / 64, IMG_ / 128, HN), 256>>>(
        ipq, ipkh, nullptr, Sip, IMG_, IPL_, DHD,
        (long long)IMG_ * DHD, (long long)IPL_ * DHD, (long long)IMG_ * IPL_);
    softmax_rows<<<HN * IMG_, 256>>>(Sip, IPL_, scale);
    gemm_tc<<<dim3(DHD / 64, IMG_ / 128, HN), 256>>>(
        Sip, ipvt, nullptr, ipO, IMG_, DHD, IPL_,
        (long long)IMG_ * IPL_, (long long)DHD * IPL_, (long long)IMG_ * DHD);

    // --- merge + output projections ---
    merge_img<<<dim3(IMG_, HN), 128>>>(O, ipO, imgin);
    merge_enc<<<dim3(TXT_, HN), 128>>>(O, encin);
    gemm_tc<<<dim3(HID_ / 64, IMG_ / 128), 256>>>(imgin, W_out, b_out, out_img, IMG_, HID_, HID_, 0, 0, 0);
    gemm_tc<<<dim3(HID_ / 64, TXT_ / 128), 256>>>(encin, W_add_out, b_add_out, out_enc, TXT_, HID_, HID_, 0, 0, 0);
}